// round 17
// baseline (speedup 1.0000x reference)
#include <cuda_runtime.h>
#include <cuda_bf16.h>
#include <cuda_pipeline.h>
#include <mma.h>
#include <cstdint>

using namespace nvcuda;

// Problem constants
#define EMBED  1024
#define NHEADS 16
#define HDIM   64
#define BATCH  4
#define SEQ    2048
#define MTOK   (BATCH * SEQ)   // 8192
#define QKV_PLANE (BATCH * NHEADS * SEQ * HDIM)   // 8388608 elems
#define ATT_PLANE (MTOK * EMBED)                  // 8388608 elems

// ---------------------------------------------------------------------------
// Scratch — proven-safe 128 MB footprint, planes recycled:
//  g_q/g_k/g_v: QKV output bf16 hi/lo planes
//  g_attn: phase1 = qkv_w planes; phase2 = attn-out planes
//  g_q:    phase3 (after attn) = out_w planes
//  d_out:  phase0 scratch = x bf16 planes (overwritten by final result)
// ---------------------------------------------------------------------------
__device__ float g_q[QKV_PLANE];
__device__ float g_k[QKV_PLANE];
__device__ float g_v[QKV_PLANE];
__device__ float g_attn[ATT_PLANE];

__device__ __forceinline__ void sp_bf16(float x, __nv_bfloat16& h, __nv_bfloat16& l)
{
    h = __float2bfloat16_rn(x);
    l = __float2bfloat16_rn(x - __bfloat162float(h));
}

__device__ __forceinline__ void st_split4(
    __nv_bfloat16* H, __nv_bfloat16* L, int off, float4 v)
{
    __nv_bfloat16 hx, lx, hy, ly, hz, lz, hw, lw;
    sp_bf16(v.x, hx, lx); sp_bf16(v.y, hy, ly);
    sp_bf16(v.z, hz, lz); sp_bf16(v.w, hw, lw);
    *(__nv_bfloat162*)(H + off)     = __nv_bfloat162(hx, hy);
    *(__nv_bfloat162*)(H + off + 2) = __nv_bfloat162(hz, hw);
    *(__nv_bfloat162*)(L + off)     = __nv_bfloat162(lx, ly);
    *(__nv_bfloat162*)(L + off + 2) = __nv_bfloat162(lz, lw);
}

__global__ __launch_bounds__(256) void split_w(
    const float* __restrict__ src,
    __nv_bfloat16* __restrict__ hp, __nv_bfloat16* __restrict__ lp)
{
    int i = blockIdx.x * 256 + threadIdx.x;
    float4 v = ((const float4*)src)[i];
    st_split4(hp, lp, 4 * i, v);
}

// ---------------------------------------------------------------------------
// GEMM geometry: block 128x128, BK=32, 512 threads = 16 warps
// (wm = w&3, wn = w>>2; warp tile 32x32). Full cp.async double buffer.
// ---------------------------------------------------------------------------
#define LDSG  40
#define MATG  (128 * LDSG)
#define BUFG  (4 * MATG)
#define GEMM_SMEM (2 * BUFG * 2 + 16 * 16 * 20 * 4)   // 102400 B
#define NKBG  (EMBED / 32)

// ---------------------------------------------------------------------------
// QKV GEMM: A = x planes (in d_out scratch), B = qkv_w planes. Full cp.async.
// Epilogue -> bf16 hi/lo planes in g_q/g_k/g_v.
// ---------------------------------------------------------------------------
__global__ __launch_bounds__(512) void gemm_qkv(
    const __nv_bfloat16* __restrict__ Ah, const __nv_bfloat16* __restrict__ Wh,
    const float* __restrict__ bias)
{
    extern __shared__ __align__(16) char dsm[];
    __nv_bfloat16* sm0 = (__nv_bfloat16*)dsm;
    float* sPatchAll   = (float*)(dsm + 2 * BUFG * 2);

    const __nv_bfloat16* Al = Ah + ATT_PLANE;
    const __nv_bfloat16* Wl = Wh + 3 * EMBED * EMBED;

    const int tid  = threadIdx.x;
    const int lane = tid & 31;
    const int w    = tid >> 5;
    const int wm   = w & 3;
    const int wn   = w >> 2;
    const int m0   = blockIdx.y * 128;
    const int n0   = blockIdx.x * 128;

    const int lrow = tid >> 2;
    const int lseg = (tid & 3) * 8;
    const __nv_bfloat16* gAh = Ah + (size_t)(m0 + lrow) * EMBED + lseg;
    const __nv_bfloat16* gAl = Al + (size_t)(m0 + lrow) * EMBED + lseg;
    const __nv_bfloat16* gWh = Wh + (size_t)(n0 + lrow) * EMBED + lseg;
    const __nv_bfloat16* gWl = Wl + (size_t)(n0 + lrow) * EMBED + lseg;
    const int off = lrow * LDSG + lseg;

    wmma::fragment<wmma::accumulator, 16, 16, 16, float> acc[2][2];
#pragma unroll
    for (int mt = 0; mt < 2; mt++)
#pragma unroll
        for (int nt = 0; nt < 2; nt++)
            wmma::fill_fragment(acc[mt][nt], 0.0f);

    auto issue = [&](__nv_bfloat16* bb, int g) {
        __pipeline_memcpy_async(bb + off,            gAh + g, 16);
        __pipeline_memcpy_async(bb + MATG + off,     gAl + g, 16);
        __pipeline_memcpy_async(bb + 2 * MATG + off, gWh + g, 16);
        __pipeline_memcpy_async(bb + 3 * MATG + off, gWl + g, 16);
        __pipeline_commit();
    };

    issue(sm0, 0);
    __pipeline_wait_prior(0);
    __syncthreads();

    for (int kb = 0; kb < NKBG; kb++) {
        if (kb + 1 < NKBG)
            issue(sm0 + ((kb + 1) & 1) * BUFG, (kb + 1) * 32);

        const __nv_bfloat16* sb  = sm0 + (kb & 1) * BUFG;
        const __nv_bfloat16* sAh = sb;
        const __nv_bfloat16* sAl = sb + MATG;
        const __nv_bfloat16* sBh = sb + 2 * MATG;
        const __nv_bfloat16* sBl = sb + 3 * MATG;
#pragma unroll
        for (int ks = 0; ks < 2; ks++) {
            const int kk = ks * 16;
            wmma::fragment<wmma::matrix_a, 16, 16, 16, __nv_bfloat16,
                           wmma::row_major> ah[2], al[2];
#pragma unroll
            for (int mt = 0; mt < 2; mt++) {
                wmma::load_matrix_sync(ah[mt], sAh + (wm * 32 + mt * 16) * LDSG + kk, LDSG);
                wmma::load_matrix_sync(al[mt], sAl + (wm * 32 + mt * 16) * LDSG + kk, LDSG);
            }
#pragma unroll
            for (int nt = 0; nt < 2; nt++) {
                wmma::fragment<wmma::matrix_b, 16, 16, 16, __nv_bfloat16,
                               wmma::col_major> bh, bl;
                wmma::load_matrix_sync(bh, sBh + (wn * 32 + nt * 16) * LDSG + kk, LDSG);
                wmma::load_matrix_sync(bl, sBl + (wn * 32 + nt * 16) * LDSG + kk, LDSG);
#pragma unroll
                for (int mt = 0; mt < 2; mt++) {
                    wmma::mma_sync(acc[mt][nt], ah[mt], bh, acc[mt][nt]);
                    wmma::mma_sync(acc[mt][nt], ah[mt], bl, acc[mt][nt]);
                    wmma::mma_sync(acc[mt][nt], al[mt], bh, acc[mt][nt]);
                }
            }
        }

        if (kb + 1 < NKBG) {
            __pipeline_wait_prior(0);
            __syncthreads();
        }
    }

    // Epilogue: bias, then bf16 hi/lo planes into g_q/g_k/g_v
    float* patch = sPatchAll + w * 320;
    const int pr = lane >> 1;
    const int pc = (lane & 1) * 8;
#pragma unroll
    for (int mt = 0; mt < 2; mt++)
#pragma unroll
        for (int nt = 0; nt < 2; nt++) {
            wmma::store_matrix_sync(patch, acc[mt][nt], 20, wmma::mem_row_major);
            __syncwarp();
            const int m = m0 + wm * 32 + mt * 16 + pr;
            const int n = n0 + wn * 32 + nt * 16 + pc;
            float f[8];
#pragma unroll
            for (int j = 0; j < 8; j++)
                f[j] = patch[pr * 20 + pc + j] + bias[n + j];
            const int b_ = m >> 11, nq = m & (SEQ - 1);
            const int which = n >> 10, e = n & 1023;
            const int h = e >> 6, d = e & 63;
            float* base = (which == 0) ? g_q : (which == 1) ? g_k : g_v;
            __nv_bfloat16* hp = (__nv_bfloat16*)base;
            __nv_bfloat16* lp = hp + QKV_PLANE;
            const size_t goff = ((((size_t)b_ * NHEADS) + h) * SEQ + nq) * HDIM + d;
#pragma unroll
            for (int j = 0; j < 8; j += 2) {
                __nv_bfloat16 h0, l0, h1, l1;
                sp_bf16(f[j], h0, l0);
                sp_bf16(f[j + 1], h1, l1);
                *(__nv_bfloat162*)(hp + goff + j) = __nv_bfloat162(h0, h1);
                *(__nv_bfloat162*)(lp + goff + j) = __nv_bfloat162(l0, l1);
            }
            __syncwarp();
        }
}

// ---------------------------------------------------------------------------
// Output-proj GEMM: identical pipeline (A planes in g_attn, W planes in g_q).
// ---------------------------------------------------------------------------
__global__ __launch_bounds__(512) void gemm_proj(
    const __nv_bfloat16* __restrict__ Ah, const __nv_bfloat16* __restrict__ Wh,
    const float* __restrict__ bias, float* __restrict__ C)
{
    extern __shared__ __align__(16) char dsm[];
    __nv_bfloat16* sm0 = (__nv_bfloat16*)dsm;
    float* sPatchAll   = (float*)(dsm + 2 * BUFG * 2);

    const __nv_bfloat16* Al = Ah + ATT_PLANE;
    const __nv_bfloat16* Wl = Wh + EMBED * EMBED;

    const int tid  = threadIdx.x;
    const int lane = tid & 31;
    const int w    = tid >> 5;
    const int wm   = w & 3;
    const int wn   = w >> 2;
    const int m0   = blockIdx.y * 128;
    const int n0   = blockIdx.x * 128;

    const int lrow = tid >> 2;
    const int lseg = (tid & 3) * 8;
    const __nv_bfloat16* gAh = Ah + (size_t)(m0 + lrow) * EMBED + lseg;
    const __nv_bfloat16* gAl = Al + (size_t)(m0 + lrow) * EMBED + lseg;
    const __nv_bfloat16* gWh = Wh + (size_t)(n0 + lrow) * EMBED + lseg;
    const __nv_bfloat16* gWl = Wl + (size_t)(n0 + lrow) * EMBED + lseg;
    const int off = lrow * LDSG + lseg;

    wmma::fragment<wmma::accumulator, 16, 16, 16, float> acc[2][2];
#pragma unroll
    for (int mt = 0; mt < 2; mt++)
#pragma unroll
        for (int nt = 0; nt < 2; nt++)
            wmma::fill_fragment(acc[mt][nt], 0.0f);

    auto issue = [&](__nv_bfloat16* bb, int g) {
        __pipeline_memcpy_async(bb + off,            gAh + g, 16);
        __pipeline_memcpy_async(bb + MATG + off,     gAl + g, 16);
        __pipeline_memcpy_async(bb + 2 * MATG + off, gWh + g, 16);
        __pipeline_memcpy_async(bb + 3 * MATG + off, gWl + g, 16);
        __pipeline_commit();
    };

    issue(sm0, 0);
    __pipeline_wait_prior(0);
    __syncthreads();

    for (int kb = 0; kb < NKBG; kb++) {
        if (kb + 1 < NKBG)
            issue(sm0 + ((kb + 1) & 1) * BUFG, (kb + 1) * 32);

        const __nv_bfloat16* sb  = sm0 + (kb & 1) * BUFG;
        const __nv_bfloat16* sAh = sb;
        const __nv_bfloat16* sAl = sb + MATG;
        const __nv_bfloat16* sBh = sb + 2 * MATG;
        const __nv_bfloat16* sBl = sb + 3 * MATG;
#pragma unroll
        for (int ks = 0; ks < 2; ks++) {
            const int kk = ks * 16;
            wmma::fragment<wmma::matrix_a, 16, 16, 16, __nv_bfloat16,
                           wmma::row_major> ah[2], al[2];
#pragma unroll
            for (int mt = 0; mt < 2; mt++) {
                wmma::load_matrix_sync(ah[mt], sAh + (wm * 32 + mt * 16) * LDSG + kk, LDSG);
                wmma::load_matrix_sync(al[mt], sAl + (wm * 32 + mt * 16) * LDSG + kk, LDSG);
            }
#pragma unroll
            for (int nt = 0; nt < 2; nt++) {
                wmma::fragment<wmma::matrix_b, 16, 16, 16, __nv_bfloat16,
                               wmma::col_major> bh, bl;
                wmma::load_matrix_sync(bh, sBh + (wn * 32 + nt * 16) * LDSG + kk, LDSG);
                wmma::load_matrix_sync(bl, sBl + (wn * 32 + nt * 16) * LDSG + kk, LDSG);
#pragma unroll
                for (int mt = 0; mt < 2; mt++) {
                    wmma::mma_sync(acc[mt][nt], ah[mt], bh, acc[mt][nt]);
                    wmma::mma_sync(acc[mt][nt], ah[mt], bl, acc[mt][nt]);
                    wmma::mma_sync(acc[mt][nt], al[mt], bh, acc[mt][nt]);
                }
            }
        }

        if (kb + 1 < NKBG) {
            __pipeline_wait_prior(0);
            __syncthreads();
        }
    }

    float* patch = sPatchAll + w * 320;
    const int pr = lane >> 1;
    const int pc = (lane & 1) * 8;
#pragma unroll
    for (int mt = 0; mt < 2; mt++)
#pragma unroll
        for (int nt = 0; nt < 2; nt++) {
            wmma::store_matrix_sync(patch, acc[mt][nt], 20, wmma::mem_row_major);
            __syncwarp();
            const int m = m0 + wm * 32 + mt * 16 + pr;
            const int n = n0 + wn * 32 + nt * 16 + pc;
            float4 q0 = *(const float4*)&patch[pr * 20 + pc];
            float4 q1 = *(const float4*)&patch[pr * 20 + pc + 4];
            float4 b0 = *(const float4*)&bias[n];
            float4 b1 = *(const float4*)&bias[n + 4];
            q0.x += b0.x; q0.y += b0.y; q0.z += b0.z; q0.w += b0.w;
            q1.x += b1.x; q1.y += b1.y; q1.z += b1.z; q1.w += b1.w;
            float* p = C + (size_t)m * EMBED + n;
            *(float4*)(p)     = q0;
            *(float4*)(p + 4) = q1;
            __syncwarp();
        }
}

// ---------------------------------------------------------------------------
// WMMA flash attention with K/V prefetch overlapped into compute phases.
// K(t+1) issued after S-store sync (K dead); V(t+1) after PV-store sync
// (V dead); wait folded into the loop-end barrier.
// ---------------------------------------------------------------------------
#define OFF_QH 0
#define OFF_QL 18432
#define OFF_KH 36864
#define OFF_KL 55296
#define OFF_VH 73728
#define OFF_VL 92160
#define OFF_S  110592
#define OFF_PH 110592
#define OFF_PL 145408
#define OFF_OS 180224
#define ATTN_SMEM_BYTES 215040

__global__ __launch_bounds__(256, 1) void attn_wmma()
{
    extern __shared__ char smc[];
    __nv_bfloat16* Qh = (__nv_bfloat16*)(smc + OFF_QH);
    __nv_bfloat16* Ql = (__nv_bfloat16*)(smc + OFF_QL);
    __nv_bfloat16* Kh = (__nv_bfloat16*)(smc + OFF_KH);
    __nv_bfloat16* Kl = (__nv_bfloat16*)(smc + OFF_KL);
    __nv_bfloat16* Vh = (__nv_bfloat16*)(smc + OFF_VH);
    __nv_bfloat16* Vl = (__nv_bfloat16*)(smc + OFF_VL);
    float*         S  = (float*)        (smc + OFF_S);
    __nv_bfloat16* Ph = (__nv_bfloat16*)(smc + OFF_PH);
    __nv_bfloat16* Pl = (__nv_bfloat16*)(smc + OFF_PL);
    float*         Os = (float*)        (smc + OFF_OS);

    const int tid  = threadIdx.x;
    const int w    = tid >> 5;
    const int wm   = w & 3;
    const int wn   = w >> 2;
    const int ty   = tid >> 4;
    const int tx   = tid & 15;
    const int bh   = blockIdx.y;
    const int q0   = blockIdx.x * 128;

    const __nv_bfloat16* qh = (const __nv_bfloat16*)g_q;
    const __nv_bfloat16* kh = (const __nv_bfloat16*)g_k;
    const __nv_bfloat16* vh = (const __nv_bfloat16*)g_v;
    const size_t tb = (size_t)bh * SEQ * HDIM;

    // loader coords: 8 rows-per-thread-step, 16B chunks
    const int lr = tid >> 3;           // 0..31 base row
    const int lc = (tid & 7) * 8;      // 0..56 col

    // prologue: Q + K(0),V(0) async
#pragma unroll
    for (int i = 0; i < 4; i++) {
        int r = lr + i * 32;
        size_t g = tb + (size_t)(q0 + r) * HDIM + lc;
        __pipeline_memcpy_async(Qh + r * 72 + lc, qh + g, 16);
        __pipeline_memcpy_async(Ql + r * 72 + lc, qh + QKV_PLANE + g, 16);
        size_t gk = tb + (size_t)r * HDIM + lc;
        __pipeline_memcpy_async(Kh + r * 72 + lc, kh + gk, 16);
        __pipeline_memcpy_async(Kl + r * 72 + lc, kh + QKV_PLANE + gk, 16);
        __pipeline_memcpy_async(Vh + r * 72 + lc, vh + gk, 16);
        __pipeline_memcpy_async(Vl + r * 72 + lc, vh + QKV_PLANE + gk, 16);
    }
    __pipeline_commit();

    float m_r[8], l_r[8], corr[8], o[8][4];
#pragma unroll
    for (int i = 0; i < 8; i++) {
        m_r[i] = -1e30f;
        l_r[i] = 0.f;
#pragma unroll
        for (int j = 0; j < 4; j++) o[i][j] = 0.f;
    }
    __pipeline_wait_prior(0);
    __syncthreads();

    for (int t = 0; t < SEQ / 128; t++) {
        // ---- S = Q K^T ----
        {
            wmma::fragment<wmma::accumulator, 16, 16, 16, float> accS[2][4];
#pragma unroll
            for (int mt = 0; mt < 2; mt++)
#pragma unroll
                for (int nt = 0; nt < 4; nt++)
                    wmma::fill_fragment(accS[mt][nt], 0.0f);

#pragma unroll
            for (int kk = 0; kk < 4; kk++) {
                const int k = kk * 16;
                wmma::fragment<wmma::matrix_a, 16, 16, 16, __nv_bfloat16,
                               wmma::row_major> ah[2], al[2];
#pragma unroll
                for (int mt = 0; mt < 2; mt++) {
                    wmma::load_matrix_sync(ah[mt], &Qh[(wm * 32 + mt * 16) * 72 + k], 72);
                    wmma::load_matrix_sync(al[mt], &Ql[(wm * 32 + mt * 16) * 72 + k], 72);
                }
#pragma unroll
                for (int nt = 0; nt < 4; nt++) {
                    wmma::fragment<wmma::matrix_b, 16, 16, 16, __nv_bfloat16,
                                   wmma::col_major> bh2, bl2;
                    wmma::load_matrix_sync(bh2, &Kh[(wn * 64 + nt * 16) * 72 + k], 72);
                    wmma::load_matrix_sync(bl2, &Kl[(wn * 64 + nt * 16) * 72 + k], 72);
#pragma unroll
                    for (int mt = 0; mt < 2; mt++) {
                        wmma::mma_sync(accS[mt][nt], ah[mt], bh2, accS[mt][nt]);
                        wmma::mma_sync(accS[mt][nt], ah[mt], bl2, accS[mt][nt]);
                        wmma::mma_sync(accS[mt][nt], al[mt], bh2, accS[mt][nt]);
                    }
                }
            }
#pragma unroll
            for (int mt = 0; mt < 2; mt++)
#pragma unroll
                for (int nt = 0; nt < 4; nt++)
                    wmma::store_matrix_sync(
                        &S[(wm * 32 + mt * 16) * 136 + wn * 64 + nt * 16],
                        accS[mt][nt], 136, wmma::mem_row_major);
        }
        __syncthreads();   // all K reads done; S visible

        // K(t+1) prefetch overlaps softmax + P-store + PV
        if (t + 1 < SEQ / 128) {
            const int k0n = (t + 1) * 128;
#pragma unroll
            for (int i = 0; i < 4; i++) {
                int r = lr + i * 32;
                size_t g = tb + (size_t)(k0n + r) * HDIM + lc;
                __pipeline_memcpy_async(Kh + r * 72 + lc, kh + g, 16);
                __pipeline_memcpy_async(Kl + r * 72 + lc, kh + QKV_PLANE + g, 16);
            }
            __pipeline_commit();
        }

        // ---- softmax ----
        float s[8][8];
#pragma unroll
        for (int r = 0; r < 8; r++) {
            *(float4*)&s[r][0] = *(const float4*)&S[(ty * 8 + r) * 136 + tx * 8];
            *(float4*)&s[r][4] = *(const float4*)&S[(ty * 8 + r) * 136 + tx * 8 + 4];
        }
#pragma unroll
        for (int r = 0; r < 8; r++) {
            float tmax = -1e30f;
#pragma unroll
            for (int c = 0; c < 8; c++) {
                s[r][c] *= 0.125f;
                tmax = fmaxf(tmax, s[r][c]);
            }
#pragma unroll
            for (int off = 8; off; off >>= 1)
                tmax = fmaxf(tmax, __shfl_xor_sync(0xffffffffu, tmax, off));
            float mnew = fmaxf(m_r[r], tmax);
            corr[r] = __expf(m_r[r] - mnew);
            m_r[r] = mnew;
            float rsum = 0.f;
#pragma unroll
            for (int c = 0; c < 8; c++) {
                float p = __expf(s[r][c] - mnew);
                s[r][c] = p;
                rsum += p;
            }
#pragma unroll
            for (int off = 8; off; off >>= 1)
                rsum += __shfl_xor_sync(0xffffffffu, rsum, off);
            l_r[r] = l_r[r] * corr[r] + rsum;
        }
        __syncthreads();   // S reads done before Ph/Pl overlay

        // vectorized P hi/lo stores
#pragma unroll
        for (int r = 0; r < 8; r++) {
            uint2 hv, lv;
            __nv_bfloat16 h0, l0, h1, l1;
            sp_bf16(s[r][0], h0, l0); sp_bf16(s[r][1], h1, l1);
            __nv_bfloat162 hp0(h0, h1), lp0(l0, l1);
            sp_bf16(s[r][2], h0, l0); sp_bf16(s[r][3], h1, l1);
            __nv_bfloat162 hp1(h0, h1), lp1(l0, l1);
            hv.x = *(uint32_t*)&hp0; hv.y = *(uint32_t*)&hp1;
            lv.x = *(uint32_t*)&lp0; lv.y = *(uint32_t*)&lp1;
            *(uint2*)&Ph[(ty * 8 + r) * 136 + tx * 8] = hv;
            *(uint2*)&Pl[(ty * 8 + r) * 136 + tx * 8] = lv;
            sp_bf16(s[r][4], h0, l0); sp_bf16(s[r][5], h1, l1);
            __nv_bfloat162 hp2(h0, h1), lp2(l0, l1);
            sp_bf16(s[r][6], h0, l0); sp_bf16(s[r][7], h1, l1);
            __nv_bfloat162 hp3(h0, h1), lp3(l0, l1);
            hv.x = *(uint32_t*)&hp2; hv.y = *(uint32_t*)&hp3;
            lv.x = *(uint32_t*)&lp2; lv.y = *(uint32_t*)&lp3;
            *(uint2*)&Ph[(ty * 8 + r) * 136 + tx * 8 + 4] = hv;
            *(uint2*)&Pl[(ty * 8 + r) * 136 + tx * 8 + 4] = lv;
        }
        __syncthreads();

        // ---- O_tile = P V ----
        {
            wmma::fragment<wmma::accumulator, 16, 16, 16, float> accO[2][2];
#pragma unroll
            for (int mt = 0; mt < 2; mt++)
#pragma unroll
                for (int nt = 0; nt < 2; nt++)
                    wmma::fill_fragment(accO[mt][nt], 0.0f);

#pragma unroll
            for (int kk = 0; kk < 8; kk++) {
                const int k = kk * 16;
                wmma::fragment<wmma::matrix_a, 16, 16, 16, __nv_bfloat16,
                               wmma::row_major> ph[2], pl[2];
#pragma unroll
                for (int mt = 0; mt < 2; mt++) {
                    wmma::load_matrix_sync(ph[mt], &Ph[(wm * 32 + mt * 16) * 136 + k], 136);
                    wmma::load_matrix_sync(pl[mt], &Pl[(wm * 32 + mt * 16) * 136 + k], 136);
                }
#pragma unroll
                for (int nt = 0; nt < 2; nt++) {
                    wmma::fragment<wmma::matrix_b, 16, 16, 16, __nv_bfloat16,
                                   wmma::row_major> vbh, vbl;
                    wmma::load_matrix_sync(vbh, &Vh[k * 72 + wn * 32 + nt * 16], 72);
                    wmma::load_matrix_sync(vbl, &Vl[k * 72 + wn * 32 + nt * 16], 72);
#pragma unroll
                    for (int mt = 0; mt < 2; mt++) {
                        wmma::mma_sync(accO[mt][nt], ph[mt], vbh, accO[mt][nt]);
                        wmma::mma_sync(accO[mt][nt], ph[mt], vbl, accO[mt][nt]);
                        wmma::mma_sync(accO[mt][nt], pl[mt], vbh, accO[mt][nt]);
                    }
                }
            }
#pragma unroll
            for (int mt = 0; mt < 2; mt++)
#pragma unroll
                for (int nt = 0; nt < 2; nt++)
                    wmma::store_matrix_sync(
                        &Os[(wm * 32 + mt * 16) * 68 + wn * 32 + nt * 16],
                        accO[mt][nt], 68, wmma::mem_row_major);
        }
        __syncthreads();   // all V reads done; Os visible

        // V(t+1) prefetch overlaps accumulate
        if (t + 1 < SEQ / 128) {
            const int k0n = (t + 1) * 128;
#pragma unroll
            for (int i = 0; i < 4; i++) {
                int r = lr + i * 32;
                size_t g = tb + (size_t)(k0n + r) * HDIM + lc;
                __pipeline_memcpy_async(Vh + r * 72 + lc, vh + g, 16);
                __pipeline_memcpy_async(Vl + r * 72 + lc, vh + QKV_PLANE + g, 16);
            }
            __pipeline_commit();
        }

        // ---- accumulate with rescale ----
#pragma unroll
        for (int r = 0; r < 8; r++) {
            float4 pv = *(const float4*)&Os[(ty * 8 + r) * 68 + tx * 4];
            o[r][0] = o[r][0] * corr[r] + pv.x;
            o[r][1] = o[r][1] * corr[r] + pv.y;
            o[r][2] = o[r][2] * corr[r] + pv.z;
            o[r][3] = o[r][3] * corr[r] + pv.w;
        }
        if (t + 1 < SEQ / 128) __pipeline_wait_prior(0);
        __syncthreads();
    }

    const int b_ = bh >> 4;
    const int hh = bh & 15;
    __nv_bfloat16* oh = (__nv_bfloat16*)g_attn;
    __nv_bfloat16* ol = oh + ATT_PLANE;
#pragma unroll
    for (int r = 0; r < 8; r++) {
        float inv = 1.0f / l_r[r];
        int n = q0 + ty * 8 + r;
        const size_t off = ((size_t)b_ * SEQ + n) * EMBED + hh * 64 + tx * 4;
        float v0 = o[r][0] * inv, v1 = o[r][1] * inv;
        float v2 = o[r][2] * inv, v3 = o[r][3] * inv;
        __nv_bfloat16 h0, l0, h1, l1, h2, l2, h3, l3;
        sp_bf16(v0, h0, l0); sp_bf16(v1, h1, l1);
        sp_bf16(v2, h2, l2); sp_bf16(v3, h3, l3);
        *(__nv_bfloat162*)(oh + off)     = __nv_bfloat162(h0, h1);
        *(__nv_bfloat162*)(oh + off + 2) = __nv_bfloat162(h2, h3);
        *(__nv_bfloat162*)(ol + off)     = __nv_bfloat162(l0, l1);
        *(__nv_bfloat162*)(ol + off + 2) = __nv_bfloat162(l2, l3);
    }
}

// ---------------------------------------------------------------------------
extern "C" void kernel_launch(void* const* d_in, const int* in_sizes, int n_in,
                              void* d_out, int out_size)
{
    (void)in_sizes; (void)n_in; (void)out_size;
    const float* x     = (const float*)d_in[0];
    const float* qkv_w = (const float*)d_in[1];
    const float* qkv_b = (const float*)d_in[2];
    const float* out_w = (const float*)d_in[3];
    const float* out_b = (const float*)d_in[4];
    float* out = (float*)d_out;

    cudaFuncSetAttribute(gemm_qkv,
                         cudaFuncAttributeMaxDynamicSharedMemorySize, GEMM_SMEM);
    cudaFuncSetAttribute(gemm_proj,
                         cudaFuncAttributeMaxDynamicSharedMemorySize, GEMM_SMEM);
    cudaFuncSetAttribute(attn_wmma,
                         cudaFuncAttributeMaxDynamicSharedMemorySize,
                         ATTN_SMEM_BYTES);

    static void* p_attn = nullptr;
    static void* p_q = nullptr;
    if (!p_attn) {
        cudaGetSymbolAddress(&p_attn, g_attn);
        cudaGetSymbolAddress(&p_q, g_q);
    }
    __nv_bfloat16* wq_h = (__nv_bfloat16*)p_attn;
    __nv_bfloat16* wq_l = wq_h + 3 * EMBED * EMBED;
    __nv_bfloat16* wo_h = (__nv_bfloat16*)p_q;
    __nv_bfloat16* wo_l = wo_h + EMBED * EMBED;
    __nv_bfloat16* x_h  = (__nv_bfloat16*)out;        // d_out as scratch
    __nv_bfloat16* x_l  = x_h + ATT_PLANE;

    // 0) split qkv_w -> g_attn planes; x -> d_out planes (scratch)
    split_w<<<3 * EMBED * EMBED / 1024, 256>>>(qkv_w, wq_h, wq_l);
    split_w<<<MTOK * EMBED / 1024, 256>>>(x, x_h, x_l);

    // 1) QKV projection (full cp.async pipeline)
    gemm_qkv<<<dim3(3 * EMBED / 128, MTOK / 128), 512, GEMM_SMEM>>>(
        x_h, wq_h, qkv_b);

    // 2) Flash attention (KV-prefetch overlapped) -> O planes in g_attn
    attn_wmma<<<dim3(SEQ / 128, BATCH * NHEADS), 256, ATTN_SMEM_BYTES>>>();

    // 3) split out_w -> g_q (dead after attention), then projection -> d_out
    split_w<<<EMBED * EMBED / 1024, 256>>>(out_w, wo_h, wo_l);
    gemm_proj<<<dim3(EMBED / 128, MTOK / 128), 512, GEMM_SMEM>>>(
        (const __nv_bfloat16*)p_attn, wo_h, out_b, out);
}